// round 2
// baseline (speedup 1.0000x reference)
#include <cuda_runtime.h>

#define SEQ   384
#define HID   128
#define TABLE 769   // 2*SEQ+1
#define BATCH 2
#define NPAIR (BATCH * SEQ * SEQ)   // 294912

// Scratch (allocation-free rule): device globals.
__device__ float g_WT[4 * HID * HID];    // [t][f][h]  (W transposed per table slice)
__device__ float g_P [4 * TABLE * HID];  // [t][row][h] = pe_t[row] @ W_t^T (+bias for t==0)

// ---------------------------------------------------------------------------
// Kernel 1: transpose W (HID x 4*HID, row-major) into per-table f-major tiles.
// WT[t][f][h] = W[h, t*HID + f]
// ---------------------------------------------------------------------------
__global__ void k_transpose_w(const float* __restrict__ W) {
    int idx = blockIdx.x * blockDim.x + threadIdx.x;
    if (idx >= 4 * HID * HID) return;
    int h = idx & (HID - 1);
    int f = (idx >> 7) & (HID - 1);
    int t = idx >> 14;
    g_WT[idx] = W[h * (4 * HID) + t * HID + f];
}

// ---------------------------------------------------------------------------
// Kernel 2: P_t = pe_t @ W_t^T  (769 x 128 each). Bias folded into t==0.
// Block: 256 threads handles 16 rows of one table. Grid: (49, 4).
// ---------------------------------------------------------------------------
__global__ void k_precompute(const float* __restrict__ pe_ss,
                             const float* __restrict__ pe_se,
                             const float* __restrict__ pe_es,
                             const float* __restrict__ pe_ee,
                             const float* __restrict__ bias) {
    __shared__ float peS[16 * HID];   // 8 KB
    const int t = blockIdx.y;
    const float* pe = (t == 0) ? pe_ss : (t == 1) ? pe_se : (t == 2) ? pe_es : pe_ee;
    const int row0 = blockIdx.x * 16;
    const int tid  = threadIdx.x;

    // Cooperative load of 16 rows (clamped) into smem.
    for (int i = tid; i < 16 * HID; i += 256) {
        int row = row0 + (i >> 7);
        row = row < TABLE ? row : TABLE - 1;
        peS[i] = pe[row * HID + (i & (HID - 1))];
    }
    __syncthreads();

    const int r2 = tid >> 7;          // 0/1: which row of each pair
    const int h  = tid & (HID - 1);   // output channel

    float acc[8];
#pragma unroll
    for (int r = 0; r < 8; ++r) acc[r] = 0.f;

    const float* WTt = g_WT + t * HID * HID;
    for (int f = 0; f < HID; ++f) {
        float w = WTt[f * HID + h];   // coalesced across threads
#pragma unroll
        for (int r = 0; r < 8; ++r)
            acc[r] += peS[(r * 2 + r2) * HID + f] * w;   // smem broadcast
    }

    const float bv = (t == 0) ? bias[h] : 0.f;
#pragma unroll
    for (int r = 0; r < 8; ++r) {
        int row = row0 + r * 2 + r2;
        if (row < TABLE) g_P[(t * TABLE + row) * HID + h] = acc[r] + bv;
    }
}

// ---------------------------------------------------------------------------
// Kernel 3: main fusion. One warp per (b,q,k) pair: 4 gathered rows summed,
// ReLU, streamed out. Each lane handles 4 channels via float4.
// ---------------------------------------------------------------------------
__global__ void k_fuse(const int* __restrict__ pos_s,
                       const int* __restrict__ pos_e,
                       float* __restrict__ out) {
    const int warp = threadIdx.x >> 5;
    const int lane = threadIdx.x & 31;
    const int pair = blockIdx.x * 8 + warp;          // grid sized exactly

    const int bb = (pair >= SEQ * SEQ) ? 1 : 0;      // BATCH == 2
    const int r  = pair - bb * SEQ * SEQ;
    const int q  = r / SEQ;
    const int k  = r - q * SEQ;

    const int base = bb * SEQ;
    const int psq = __ldg(pos_s + base + q);
    const int peq = __ldg(pos_e + base + q);
    const int psk = __ldg(pos_s + base + k);
    const int pek = __ldg(pos_e + base + k);

    const int iss = psq - psk + SEQ;
    const int ise = psq - pek + SEQ;
    const int ies = peq - psk + SEQ;
    const int iee = peq - pek + SEQ;

    const float4* Pss = reinterpret_cast<const float4*>(g_P + (0 * TABLE + iss) * HID) + lane;
    const float4* Pse = reinterpret_cast<const float4*>(g_P + (1 * TABLE + ise) * HID) + lane;
    const float4* Pes = reinterpret_cast<const float4*>(g_P + (2 * TABLE + ies) * HID) + lane;
    const float4* Pee = reinterpret_cast<const float4*>(g_P + (3 * TABLE + iee) * HID) + lane;

    float4 a = __ldg(Pss);
    float4 c = __ldg(Pse);
    float4 d = __ldg(Pes);
    float4 e = __ldg(Pee);

    float4 v;
    v.x = fmaxf(a.x + c.x + d.x + e.x, 0.f);
    v.y = fmaxf(a.y + c.y + d.y + e.y, 0.f);
    v.z = fmaxf(a.z + c.z + d.z + e.z, 0.f);
    v.w = fmaxf(a.w + c.w + d.w + e.w, 0.f);

    float4* o = reinterpret_cast<float4*>(out + (size_t)pair * HID) + lane;
    __stcs(o, v);   // streaming store: don't evict the P tables from L2
}

// ---------------------------------------------------------------------------
extern "C" void kernel_launch(void* const* d_in, const int* in_sizes, int n_in,
                              void* d_out, int out_size) {
    const int*   pos_s = (const int*)  d_in[0];
    const int*   pos_e = (const int*)  d_in[1];
    const float* pe_ss = (const float*)d_in[2];
    const float* pe_se = (const float*)d_in[3];
    const float* pe_es = (const float*)d_in[4];
    const float* pe_ee = (const float*)d_in[5];
    const float* W     = (const float*)d_in[6];
    const float* bias  = (const float*)d_in[7];
    float* out = (float*)d_out;

    k_transpose_w<<<(4 * HID * HID + 255) / 256, 256>>>(W);

    dim3 g2((TABLE + 15) / 16, 4);
    k_precompute<<<g2, 256>>>(pe_ss, pe_se, pe_es, pe_ee, bias);

    k_fuse<<<NPAIR / 8, 256>>>(pos_s, pos_e, out);
}

// round 3
// speedup vs baseline: 1.0883x; 1.0883x over previous
#include <cuda_runtime.h>

#define SEQ   384
#define HID   128
#define TAB   769   // 2*SEQ+1
#define BATCH 2
#define NPAIR (BATCH * SEQ * SEQ)   // 294912

// Scratch (allocation-free rule): device globals.
__device__ float g_WT[4 * HID * HID];     // [t][f][h]
__device__ float g_P [4 * TAB * HID];     // [t][row][h] = pe_t[row] @ W_t^T (+bias for t==0)
__device__ float g_AC[16 * TAB * HID];    // t<8: A_dq[row]=P0[row]+P2[row+dq]; t>=8: C_dq[row]=P1[row]+P3[row+dq]
__device__ float g_D [64 * TAB * HID];    // [(dq*8+dk)][row][h] = relu(A_dq[row] + C_dq[row-dk])  (25.2 MB)

// ---------------------------------------------------------------------------
// Kernel 1: transpose W (HID x 4*HID row-major) -> WT[t][f][h]
// ---------------------------------------------------------------------------
__global__ void k_transpose_w(const float* __restrict__ W) {
    int idx = blockIdx.x * blockDim.x + threadIdx.x;
    if (idx >= 4 * HID * HID) return;
    int h = idx & (HID - 1);
    int f = (idx >> 7) & (HID - 1);
    int t = idx >> 14;
    g_WT[idx] = W[h * (4 * HID) + t * HID + f];
}

// ---------------------------------------------------------------------------
// Kernel 2: P_t = pe_t @ W_t^T  (769 x 128 each). Bias folded into t==0.
// ---------------------------------------------------------------------------
__global__ void k_precompute(const float* __restrict__ pe_ss,
                             const float* __restrict__ pe_se,
                             const float* __restrict__ pe_es,
                             const float* __restrict__ pe_ee,
                             const float* __restrict__ bias) {
    __shared__ float peS[16 * HID];
    const int t = blockIdx.y;
    const float* pe = (t == 0) ? pe_ss : (t == 1) ? pe_se : (t == 2) ? pe_es : pe_ee;
    const int row0 = blockIdx.x * 16;
    const int tid  = threadIdx.x;

    for (int i = tid; i < 16 * HID; i += 256) {
        int row = row0 + (i >> 7);
        row = row < TAB ? row : TAB - 1;
        peS[i] = pe[row * HID + (i & (HID - 1))];
    }
    __syncthreads();

    const int r2 = tid >> 7;
    const int h  = tid & (HID - 1);

    float acc[8];
#pragma unroll
    for (int r = 0; r < 8; ++r) acc[r] = 0.f;

    const float* WTt = g_WT + t * HID * HID;
    for (int f = 0; f < HID; ++f) {
        float w = WTt[f * HID + h];
#pragma unroll
        for (int r = 0; r < 8; ++r)
            acc[r] += peS[(r * 2 + r2) * HID + f] * w;
    }

    const float bv = (t == 0) ? bias[h] : 0.f;
#pragma unroll
    for (int r = 0; r < 8; ++r) {
        int row = row0 + r * 2 + r2;
        if (row < TAB) g_P[(t * TAB + row) * HID + h] = acc[r] + bv;
    }
}

// ---------------------------------------------------------------------------
// Kernel 3 (stage 2a): A/C intermediate tables, float4-vectorized.
//   t in [0,8):  AC[t][row] = P0[row] + P2[min(row+t,768)]
//   t in [8,16): AC[t][row] = P1[row] + P3[min(row+t-8,768)]
// ---------------------------------------------------------------------------
__global__ void k_build_ac() {
    int idx = blockIdx.x * 256 + threadIdx.x;        // over 16*TAB*32 float4s
    int h4   = idx & 31;
    int rest = idx >> 5;
    int row  = rest % TAB;
    int t    = rest / TAB;
    int dq   = t & 7;
    int rowq = row + dq; rowq = rowq < TAB ? rowq : TAB - 1;

    const float4* P4 = reinterpret_cast<const float4*>(g_P);
    float4 a, b;
    if (t < 8) {
        a = P4[(0 * TAB + row)  * 32 + h4];
        b = P4[(2 * TAB + rowq) * 32 + h4];
    } else {
        a = P4[(1 * TAB + row)  * 32 + h4];
        b = P4[(3 * TAB + rowq) * 32 + h4];
    }
    float4 v = {a.x + b.x, a.y + b.y, a.z + b.z, a.w + b.w};
    reinterpret_cast<float4*>(g_AC)[idx] = v;
}

// ---------------------------------------------------------------------------
// Kernel 4 (stage 2b): D[dq*8+dk][row] = relu(A_dq[row] + C_dq[max(row-dk,0)])
// ---------------------------------------------------------------------------
__global__ void k_build_d() {
    int idx = blockIdx.x * 256 + threadIdx.x;        // over 64*TAB*32 float4s
    int h4   = idx & 31;
    int rest = idx >> 5;
    int row  = rest % TAB;
    int slab = rest / TAB;                           // dq*8 + dk
    int dq   = slab >> 3;
    int dk   = slab & 7;
    int rowk = row - dk; rowk = rowk > 0 ? rowk : 0;

    const float4* AC4 = reinterpret_cast<const float4*>(g_AC);
    float4 a = AC4[(dq       * TAB + row ) * 32 + h4];
    float4 c = AC4[((8 + dq) * TAB + rowk) * 32 + h4];
    float4 v;
    v.x = fmaxf(a.x + c.x, 0.f);
    v.y = fmaxf(a.y + c.y, 0.f);
    v.z = fmaxf(a.z + c.z, 0.f);
    v.w = fmaxf(a.w + c.w, 0.f);
    reinterpret_cast<float4*>(g_D)[idx] = v;
}

// ---------------------------------------------------------------------------
// Kernel 5: main gather-copy. One warp handles 4 consecutive pairs (same q).
// Each pair: 1x LDG.128/lane from D (L2-resident) + 1x streaming STG.128/lane.
// ---------------------------------------------------------------------------
__global__ void k_fuse(const int* __restrict__ pos_s,
                       const int* __restrict__ pos_e,
                       float* __restrict__ out) {
    const int warp = threadIdx.x >> 5;
    const int lane = threadIdx.x & 31;
    const int g    = blockIdx.x * 8 + warp;
    const int pair0 = g * 4;                         // SEQ%4==0: same (b,q) for all 4

    const int bb = (pair0 >= SEQ * SEQ) ? 1 : 0;     // BATCH == 2
    const int r  = pair0 - bb * SEQ * SEQ;
    const int q  = r / SEQ;
    const int k0 = r - q * SEQ;
    const int base = bb * SEQ;

    const int psq = __ldg(pos_s + base + q);
    const int dq  = __ldg(pos_e + base + q) - psq;

    const float4* srcs[4];
#pragma unroll
    for (int j = 0; j < 4; ++j) {
        const int psk = __ldg(pos_s + base + k0 + j);
        const int dk  = __ldg(pos_e + base + k0 + j) - psk;
        const int i   = psq - psk + SEQ;
        srcs[j] = reinterpret_cast<const float4*>(
                      g_D + ((size_t)(dq * 8 + dk) * TAB + i) * HID) + lane;
    }

    float4 v0 = __ldg(srcs[0]);
    float4 v1 = __ldg(srcs[1]);
    float4 v2 = __ldg(srcs[2]);
    float4 v3 = __ldg(srcs[3]);

    float4* o = reinterpret_cast<float4*>(out + (size_t)pair0 * HID) + lane;
    __stcs(o + 0 * 32, v0);
    __stcs(o + 1 * 32, v1);
    __stcs(o + 2 * 32, v2);
    __stcs(o + 3 * 32, v3);
}

// ---------------------------------------------------------------------------
extern "C" void kernel_launch(void* const* d_in, const int* in_sizes, int n_in,
                              void* d_out, int out_size) {
    const int*   pos_s = (const int*)  d_in[0];
    const int*   pos_e = (const int*)  d_in[1];
    const float* pe_ss = (const float*)d_in[2];
    const float* pe_se = (const float*)d_in[3];
    const float* pe_es = (const float*)d_in[4];
    const float* pe_ee = (const float*)d_in[5];
    const float* W     = (const float*)d_in[6];
    const float* bias  = (const float*)d_in[7];
    float* out = (float*)d_out;

    k_transpose_w<<<(4 * HID * HID + 255) / 256, 256>>>(W);

    dim3 g2((TAB + 15) / 16, 4);
    k_precompute<<<g2, 256>>>(pe_ss, pe_se, pe_es, pe_ee, bias);

    k_build_ac<<<(16 * TAB * 32 + 255) / 256, 256>>>();
    k_build_d <<<(64 * TAB * 32 + 255) / 256, 256>>>();

    k_fuse<<<NPAIR / 4 / 8, 256>>>(pos_s, pos_e, out);
}

// round 8
// speedup vs baseline: 1.2006x; 1.1031x over previous
#include <cuda_runtime.h>
#include <cuda_fp16.h>

#define SEQ   384
#define HID   128
#define TAB   769   // 2*SEQ+1
#define BATCH 2
#define NPAIR (BATCH * SEQ * SEQ)   // 294912
#define RCH   32    // rows per build_d block

// Scratch (allocation-free rule): device globals.
__device__ float  g_WT[4 * HID * HID];       // [t][f][h]
__device__ float  g_P [4 * TAB * HID];       // [t][row][h] = pe_t[row] @ W_t^T (+bias for t==0)
__device__ __half g_Dh[64 * TAB * HID];      // [(dq*8+dk)][row][h] fp16 (12.6 MB, L2-resident)

// ---------------------------------------------------------------------------
// Kernel 1: tiled transpose W (HID x 4*HID row-major) -> WT[t][f][h].
// ---------------------------------------------------------------------------
__global__ void k_transpose_w(const float* __restrict__ W) {
    __shared__ float tile[32][33];
    const int t  = blockIdx.z;
    const int f0 = blockIdx.x * 32;
    const int h0 = blockIdx.y * 32;
    const int tx = threadIdx.x;      // 0..31
    const int ty = threadIdx.y;      // 0..7

#pragma unroll
    for (int j = 0; j < 4; ++j) {
        int h = h0 + ty + j * 8;
        tile[ty + j * 8][tx] = W[h * (4 * HID) + t * HID + f0 + tx];
    }
    __syncthreads();
#pragma unroll
    for (int j = 0; j < 4; ++j) {
        int f = f0 + ty + j * 8;
        g_WT[(t * HID + f) * HID + h0 + tx] = tile[tx][ty + j * 8];
    }
}

// ---------------------------------------------------------------------------
// Kernel 2: P_t = pe_t @ W_t^T  (769 x 128 each). Bias folded into t==0.
// ---------------------------------------------------------------------------
__global__ void k_precompute(const float* __restrict__ pe_ss,
                             const float* __restrict__ pe_se,
                             const float* __restrict__ pe_es,
                             const float* __restrict__ pe_ee,
                             const float* __restrict__ bias) {
    __shared__ float peS[16 * HID];
    const int t = blockIdx.y;
    const float* pe = (t == 0) ? pe_ss : (t == 1) ? pe_se : (t == 2) ? pe_es : pe_ee;
    const int row0 = blockIdx.x * 16;
    const int tid  = threadIdx.x;

    for (int i = tid; i < 16 * HID; i += 256) {
        int row = row0 + (i >> 7);
        row = row < TAB ? row : TAB - 1;
        peS[i] = pe[row * HID + (i & (HID - 1))];
    }
    __syncthreads();

    const int r2 = tid >> 7;
    const int h  = tid & (HID - 1);

    float acc[8];
#pragma unroll
    for (int r = 0; r < 8; ++r) acc[r] = 0.f;

    const float* WTt = g_WT + t * HID * HID;
    for (int f = 0; f < HID; ++f) {
        float w = WTt[f * HID + h];
#pragma unroll
        for (int r = 0; r < 8; ++r)
            acc[r] += peS[(r * 2 + r2) * HID + f] * w;
    }

    const float bv = (t == 0) ? bias[h] : 0.f;
#pragma unroll
    for (int r = 0; r < 8; ++r) {
        int row = row0 + r * 2 + r2;
        if (row < TAB) g_P[(t * TAB + row) * HID + h] = acc[r] + bv;
    }
}

// ---------------------------------------------------------------------------
// Kernel 3: fused D build. Block = (row-chunk, dq). Stages A_dq / C_dq windows
// in smem, then each output f4 costs ~1 LDS.128 + 1 STG.64 (fp16).
//   A_dq[r] = P0[r] + P2[r+dq]
//   C_dq[j] = P1[j] + P3[j+dq]
//   D[dq*8+dk][r] = relu(A_dq[r] + C_dq[r-dk])     (clamped rows never read)
// ---------------------------------------------------------------------------
__global__ void k_build_d() {
    __shared__ float As[RCH * HID];         // 16 KB
    __shared__ float Cs[(RCH + 7) * HID];   // 19.5 KB
    const int dq  = blockIdx.y;
    const int r0  = blockIdx.x * RCH;
    const int tid = threadIdx.x;
    const float4* P4 = reinterpret_cast<const float4*>(g_P);

    for (int i = tid; i < RCH * 32; i += 256) {
        int r = i >> 5, h4 = i & 31;
        int row  = r0 + r;    if (row  > TAB - 1) row  = TAB - 1;
        int rowq = row + dq;  if (rowq > TAB - 1) rowq = TAB - 1;
        float4 a = P4[(0 * TAB + row)  * 32 + h4];
        float4 b = P4[(2 * TAB + rowq) * 32 + h4];
        reinterpret_cast<float4*>(As)[i] = make_float4(a.x+b.x, a.y+b.y, a.z+b.z, a.w+b.w);
    }
    for (int i = tid; i < (RCH + 7) * 32; i += 256) {
        int r = i >> 5, h4 = i & 31;
        int row = r0 - 7 + r;
        if (row < 0) row = 0;
        if (row > TAB - 1) row = TAB - 1;
        int rowq = row + dq;  if (rowq > TAB - 1) rowq = TAB - 1;
        float4 a = P4[(1 * TAB + row)  * 32 + h4];
        float4 b = P4[(3 * TAB + rowq) * 32 + h4];
        reinterpret_cast<float4*>(Cs)[i] = make_float4(a.x+b.x, a.y+b.y, a.z+b.z, a.w+b.w);
    }
    __syncthreads();

    uint2* D2 = reinterpret_cast<uint2*>(g_Dh);   // 8 B = 4 halves per h4
    for (int i = tid; i < RCH * 32; i += 256) {   // 4 iters
        int r = i >> 5, h4 = i & 31;
        int row = r0 + r;
        if (row > TAB - 1) continue;
        float4 a = reinterpret_cast<const float4*>(As)[i];
#pragma unroll
        for (int dk = 0; dk < 8; ++dk) {
            float4 c = reinterpret_cast<const float4*>(Cs)[(r + 7 - dk) * 32 + h4];
            __half2 lo = __floats2half2_rn(fmaxf(a.x + c.x, 0.f), fmaxf(a.y + c.y, 0.f));
            __half2 hi = __floats2half2_rn(fmaxf(a.z + c.z, 0.f), fmaxf(a.w + c.w, 0.f));
            uint2 u;
            u.x = *reinterpret_cast<const unsigned*>(&lo);
            u.y = *reinterpret_cast<const unsigned*>(&hi);
            D2[(((dq * 8 + dk) * TAB + row) * 32) + h4] = u;
        }
    }
}

// ---------------------------------------------------------------------------
// Kernel 4: main gather. One warp handles 4 consecutive pairs (same b,q).
// Per pair: 8 B/lane fp16 read from L2-resident D, convert, 16 B/lane stream out.
// ---------------------------------------------------------------------------
__global__ void k_fuse(const int* __restrict__ pos_s,
                       const int* __restrict__ pos_e,
                       float* __restrict__ out) {
    const int warp  = threadIdx.x >> 5;
    const int lane  = threadIdx.x & 31;
    const int g     = blockIdx.x * 8 + warp;
    const int pair0 = g * 4;

    const int bb = (pair0 >= SEQ * SEQ) ? 1 : 0;     // BATCH == 2
    const int r  = pair0 - bb * SEQ * SEQ;
    const int q  = r / SEQ;
    const int k0 = r - q * SEQ;
    const int base = bb * SEQ;

    const int psq = __ldg(pos_s + base + q);
    const int dq  = __ldg(pos_e + base + q) - psq;

    const uint2* D2 = reinterpret_cast<const uint2*>(g_Dh);
    const uint2* srcs[4];
#pragma unroll
    for (int j = 0; j < 4; ++j) {
        const int psk = __ldg(pos_s + base + k0 + j);
        const int dk  = __ldg(pos_e + base + k0 + j) - psk;
        const int i   = psq - psk + SEQ;
        srcs[j] = D2 + ((size_t)(dq * 8 + dk) * TAB + i) * 32 + lane;
    }

    uint2 u[4];
#pragma unroll
    for (int j = 0; j < 4; ++j) u[j] = __ldg(srcs[j]);

    float4* o = reinterpret_cast<float4*>(out + (size_t)pair0 * HID) + lane;
#pragma unroll
    for (int j = 0; j < 4; ++j) {
        __half2 lo = *reinterpret_cast<__half2*>(&u[j].x);
        __half2 hi = *reinterpret_cast<__half2*>(&u[j].y);
        float2 f0 = __half22float2(lo);
        float2 f1 = __half22float2(hi);
        __stcs(o + j * 32, make_float4(f0.x, f0.y, f1.x, f1.y));
    }
}

// ---------------------------------------------------------------------------
extern "C" void kernel_launch(void* const* d_in, const int* in_sizes, int n_in,
                              void* d_out, int out_size) {
    const int*   pos_s = (const int*)  d_in[0];
    const int*   pos_e = (const int*)  d_in[1];
    const float* pe_ss = (const float*)d_in[2];
    const float* pe_se = (const float*)d_in[3];
    const float* pe_es = (const float*)d_in[4];
    const float* pe_ee = (const float*)d_in[5];
    const float* W     = (const float*)d_in[6];
    const float* bias  = (const float*)d_in[7];
    float* out = (float*)d_out;

    dim3 g1(4, 4, 4);                 // f-tiles, h-tiles, t
    k_transpose_w<<<g1, dim3(32, 8)>>>(W);

    dim3 g2((TAB + 15) / 16, 4);
    k_precompute<<<g2, 256>>>(pe_ss, pe_se, pe_es, pe_ee, bias);

    dim3 g3((TAB + RCH - 1) / RCH, 8);   // 25 x 8
    k_build_d<<<g3, 256>>>();

    k_fuse<<<NPAIR / 4 / 8, 256>>>(pos_s, pos_e, out);
}

// round 11
// speedup vs baseline: 1.2541x; 1.0446x over previous
#include <cuda_runtime.h>
#include <cuda_fp16.h>

#define SEQ   384
#define HID   128
#define TAB   769   // 2*SEQ+1
#define BATCH 2
#define NPAIR (BATCH * SEQ * SEQ)   // 294912
#define RCH   32    // rows per build_d block
#define PRR   16    // table rows per precompute block

// Scratch (allocation-free rule): device globals.
__device__ float  g_P [4 * TAB * HID];       // [t][row][h] = pe_t[row] @ W_t^T (+bias for t==0)
__device__ __half g_Dh[64 * TAB * HID];      // [(dq*8+dk)][row][h] fp16 (12.6 MB, L2-resident)

// ---------------------------------------------------------------------------
// Kernel 1: P_t = pe_t @ W_t^T  (769 x 128 each), W read directly (transpose
// fused via smem staging). Bias folded into t==0.
// Block: 256 threads = 8 row-groups x 32 h-quads; thread tile 2 rows x 4 h.
// ---------------------------------------------------------------------------
__global__ void __launch_bounds__(256) k_precompute(
        const float* __restrict__ pe_ss, const float* __restrict__ pe_se,
        const float* __restrict__ pe_es, const float* __restrict__ pe_ee,
        const float* __restrict__ W,     const float* __restrict__ bias) {
    __shared__ float peS[PRR * HID];     // 8 KB
    __shared__ float Ws[32 * 132];       // 16.9 KB, padded stride 132 (16B-aligned rows)

    const int t    = blockIdx.y;
    const int row0 = blockIdx.x * PRR;
    const int tid  = threadIdx.x;
    const float* pe = (t == 0) ? pe_ss : (t == 1) ? pe_se : (t == 2) ? pe_es : pe_ee;

    // Stage PRR pe rows (clamped), float4.
    const float4* pe4 = reinterpret_cast<const float4*>(pe);
    for (int i = tid; i < PRR * 32; i += 256) {
        int row = row0 + (i >> 5);
        row = row < TAB ? row : TAB - 1;
        reinterpret_cast<float4*>(peS)[i] = pe4[row * 32 + (i & 31)];
    }

    const int h0   = (tid & 31) * 4;     // 4 output channels
    const int rgrp = tid >> 5;           // 2 rows: rgrp*2, rgrp*2+1

    float acc[2][4] = {{0.f,0.f,0.f,0.f},{0.f,0.f,0.f,0.f}};

    for (int f0 = 0; f0 < HID; f0 += 32) {
        __syncthreads();
        // Stage Ws[f][h] = W[h][t*128 + f0 + f]; coalesced read (f fastest).
        for (int i = tid; i < 32 * 128; i += 256) {
            int f = i & 31, h = i >> 5;
            Ws[f * 132 + h] = W[h * (4 * HID) + t * HID + f0 + f];
        }
        __syncthreads();

#pragma unroll
        for (int f = 0; f < 32; ++f) {
            float4 w = *reinterpret_cast<const float4*>(&Ws[f * 132 + h0]);
            float p0 = peS[(rgrp * 2 + 0) * HID + f0 + f];   // warp broadcast
            float p1 = peS[(rgrp * 2 + 1) * HID + f0 + f];
            acc[0][0] += p0 * w.x; acc[0][1] += p0 * w.y;
            acc[0][2] += p0 * w.z; acc[0][3] += p0 * w.w;
            acc[1][0] += p1 * w.x; acc[1][1] += p1 * w.y;
            acc[1][2] += p1 * w.z; acc[1][3] += p1 * w.w;
        }
    }

    float4 bv = make_float4(0.f, 0.f, 0.f, 0.f);
    if (t == 0) bv = *reinterpret_cast<const float4*>(bias + h0);
#pragma unroll
    for (int rr = 0; rr < 2; ++rr) {
        int row = row0 + rgrp * 2 + rr;
        if (row < TAB) {
            float4 v = make_float4(acc[rr][0] + bv.x, acc[rr][1] + bv.y,
                                   acc[rr][2] + bv.z, acc[rr][3] + bv.w);
            reinterpret_cast<float4*>(g_P)[((t * TAB + row) * 32) + (h0 >> 2)] = v;
        }
    }
}

// ---------------------------------------------------------------------------
// Kernel 2: fused D build. Block = (row-chunk, dq). Stages A_dq / C_dq windows
// in smem; each output f4 costs ~1 LDS.128 + 1 STG.64 (fp16).
//   A_dq[r] = P0[r] + P2[r+dq]
//   C_dq[j] = P1[j] + P3[j+dq]
//   D[dq*8+dk][r] = relu(A_dq[r] + C_dq[r-dk])     (clamped rows never read)
// ---------------------------------------------------------------------------
__global__ void k_build_d() {
    __shared__ float As[RCH * HID];         // 16 KB
    __shared__ float Cs[(RCH + 7) * HID];   // 19.5 KB
    const int dq  = blockIdx.y;
    const int r0  = blockIdx.x * RCH;
    const int tid = threadIdx.x;
    const float4* P4 = reinterpret_cast<const float4*>(g_P);

    for (int i = tid; i < RCH * 32; i += 256) {
        int r = i >> 5, h4 = i & 31;
        int row  = r0 + r;    if (row  > TAB - 1) row  = TAB - 1;
        int rowq = row + dq;  if (rowq > TAB - 1) rowq = TAB - 1;
        float4 a = P4[(0 * TAB + row)  * 32 + h4];
        float4 b = P4[(2 * TAB + rowq) * 32 + h4];
        reinterpret_cast<float4*>(As)[i] = make_float4(a.x+b.x, a.y+b.y, a.z+b.z, a.w+b.w);
    }
    for (int i = tid; i < (RCH + 7) * 32; i += 256) {
        int r = i >> 5, h4 = i & 31;
        int row = r0 - 7 + r;
        if (row < 0) row = 0;
        if (row > TAB - 1) row = TAB - 1;
        int rowq = row + dq;  if (rowq > TAB - 1) rowq = TAB - 1;
        float4 a = P4[(1 * TAB + row)  * 32 + h4];
        float4 b = P4[(3 * TAB + rowq) * 32 + h4];
        reinterpret_cast<float4*>(Cs)[i] = make_float4(a.x+b.x, a.y+b.y, a.z+b.z, a.w+b.w);
    }
    __syncthreads();

    uint2* D2 = reinterpret_cast<uint2*>(g_Dh);
    for (int i = tid; i < RCH * 32; i += 256) {   // 4 iters
        int r = i >> 5, h4 = i & 31;
        int row = r0 + r;
        if (row > TAB - 1) continue;
        float4 a = reinterpret_cast<const float4*>(As)[i];
#pragma unroll
        for (int dk = 0; dk < 8; ++dk) {
            float4 c = reinterpret_cast<const float4*>(Cs)[(r + 7 - dk) * 32 + h4];
            __half2 lo = __floats2half2_rn(fmaxf(a.x + c.x, 0.f), fmaxf(a.y + c.y, 0.f));
            __half2 hi = __floats2half2_rn(fmaxf(a.z + c.z, 0.f), fmaxf(a.w + c.w, 0.f));
            uint2 u;
            u.x = *reinterpret_cast<const unsigned*>(&lo);
            u.y = *reinterpret_cast<const unsigned*>(&hi);
            D2[(((dq * 8 + dk) * TAB + row) * 32) + h4] = u;
        }
    }
}

// ---------------------------------------------------------------------------
// Kernel 3: main gather. One warp handles 8 consecutive pairs (same b,q;
// 64 | 384 so whole block shares q). Vectorized pos loads, batched D reads,
// then 8 converts + streaming STG.128.
// ---------------------------------------------------------------------------
__global__ void __launch_bounds__(256) k_fuse(
        const int* __restrict__ pos_s, const int* __restrict__ pos_e,
        float* __restrict__ out) {
    const int warp  = threadIdx.x >> 5;
    const int lane  = threadIdx.x & 31;
    const int g     = blockIdx.x * 8 + warp;
    const int pair0 = g * 8;

    const int bb = (pair0 >= SEQ * SEQ) ? 1 : 0;     // BATCH == 2
    const int r  = pair0 - bb * SEQ * SEQ;
    const int q  = r / SEQ;
    const int k0 = r - q * SEQ;
    const int base = bb * SEQ;

    const int psq = __ldg(pos_s + base + q);
    const int dq8 = (__ldg(pos_e + base + q) - psq) * 8;

    const int4 s0 = *reinterpret_cast<const int4*>(pos_s + base + k0);
    const int4 s1 = *reinterpret_cast<const int4*>(pos_s + base + k0 + 4);
    const int4 e0 = *reinterpret_cast<const int4*>(pos_e + base + k0);
    const int4 e1 = *reinterpret_cast<const int4*>(pos_e + base + k0 + 4);

    int off[8];
    off[0] = ((dq8 + e0.x - s0.x) * TAB + (psq - s0.x + SEQ)) * 32;
    off[1] = ((dq8 + e0.y - s0.y) * TAB + (psq - s0.y + SEQ)) * 32;
    off[2] = ((dq8 + e0.z - s0.z) * TAB + (psq - s0.z + SEQ)) * 32;
    off[3] = ((dq8 + e0.w - s0.w) * TAB + (psq - s0.w + SEQ)) * 32;
    off[4] = ((dq8 + e1.x - s1.x) * TAB + (psq - s1.x + SEQ)) * 32;
    off[5] = ((dq8 + e1.y - s1.y) * TAB + (psq - s1.y + SEQ)) * 32;
    off[6] = ((dq8 + e1.z - s1.z) * TAB + (psq - s1.z + SEQ)) * 32;
    off[7] = ((dq8 + e1.w - s1.w) * TAB + (psq - s1.w + SEQ)) * 32;

    const uint2* D2 = reinterpret_cast<const uint2*>(g_Dh) + lane;
    uint2 u[8];
#pragma unroll
    for (int j = 0; j < 8; ++j) u[j] = __ldg(D2 + off[j]);

    float4* o = reinterpret_cast<float4*>(out + (size_t)pair0 * HID) + lane;
#pragma unroll
    for (int j = 0; j < 8; ++j) {
        __half2 lo = *reinterpret_cast<__half2*>(&u[j].x);
        __half2 hi = *reinterpret_cast<__half2*>(&u[j].y);
        float2 f0 = __half22float2(lo);
        float2 f1 = __half22float2(hi);
        __stcs(o + j * 32, make_float4(f0.x, f0.y, f1.x, f1.y));
    }
}

// ---------------------------------------------------------------------------
extern "C" void kernel_launch(void* const* d_in, const int* in_sizes, int n_in,
                              void* d_out, int out_size) {
    const int*   pos_s = (const int*)  d_in[0];
    const int*   pos_e = (const int*)  d_in[1];
    const float* pe_ss = (const float*)d_in[2];
    const float* pe_se = (const float*)d_in[3];
    const float* pe_es = (const float*)d_in[4];
    const float* pe_ee = (const float*)d_in[5];
    const float* W     = (const float*)d_in[6];
    const float* bias  = (const float*)d_in[7];
    float* out = (float*)d_out;

    dim3 g1((TAB + PRR - 1) / PRR, 4);       // 49 x 4
    k_precompute<<<g1, 256>>>(pe_ss, pe_se, pe_es, pe_ee, W, bias);

    dim3 g2((TAB + RCH - 1) / RCH, 8);       // 25 x 8
    k_build_d<<<g2, 256>>>();

    k_fuse<<<NPAIR / 8 / 8, 256>>>(pos_s, pos_e, out);
}